// round 3
// baseline (speedup 1.0000x reference)
#include <cuda_runtime.h>
#include <math.h>

#define BATCH 4096
#define HLEN  200
#define XD    384
#define H1    200
#define H2    80
#define BN_EPS 1e-5f

// ---------------- device scratch (static allocation only) ----------------
__device__ float g_x[BATCH * XD];     // concat(u, it, pooled)
__device__ float g_y1[BATCH * H1];
__device__ float g_y2[BATCH * H2];
__device__ float g_sum[XD];
__device__ float g_sumsq[XD];
__device__ float g_scale[XD];
__device__ float g_shift[XD];
__device__ int   g_first_inactive;

// ---------------- kernels ----------------

__global__ void init_kernel() {
    int t = threadIdx.x;
    if (t < XD) { g_sum[t] = 0.f; g_sumsq[t] = 0.f; }
    if (t == 0) g_first_inactive = BATCH;
}

// outer-break semantics: first row b with history[b,0]==0 deactivates rows >= b
__global__ void scan_kernel(const int* __restrict__ history) {
    int b = blockIdx.x * blockDim.x + threadIdx.x;
    if (b < BATCH && history[b * HLEN] == 0) atomicMin(&g_first_inactive, b);
}

// one CTA per batch row; 128 threads = one per output dim
__global__ void embed_kernel(const int* __restrict__ user,
                             const int* __restrict__ item,
                             const int* __restrict__ history,
                             const int* __restrict__ cate_list,
                             const float* __restrict__ uW,   // [100000,128]
                             const float* __restrict__ iW,   // [100000,64]
                             const float* __restrict__ cW) { // [1000,64]
    int b = blockIdx.x;
    int d = threadIdx.x; // 0..127
    __shared__ int ids[HLEN];
    __shared__ int s_count;

    if (d == 0) s_count = HLEN;
    for (int l = d; l < HLEN; l += 128) ids[l] = history[b * HLEN + l];
    __syncthreads();
    for (int l = d; l < HLEN; l += 128)
        if (ids[l] == 0) atomicMin(&s_count, l);

    // independent work while the count settles
    float uv = uW[user[b] * 128 + d];
    int iid = item[b];
    float itv = (d < 64) ? iW[iid * 64 + d]
                         : cW[cate_list[iid] * 64 + (d - 64)];
    __syncthreads();

    int n = (b < g_first_inactive) ? s_count : 0;

    float acc = 0.f;
    if (d < 64) {
        #pragma unroll 4
        for (int l = 0; l < n; l++) acc += iW[ids[l] * 64 + d];
    } else {
        int dd = d - 64;
        #pragma unroll 4
        for (int l = 0; l < n; l++) acc += cW[cate_list[ids[l]] * 64 + dd];
    }
    float cnt = (float)(n > 0 ? n : 1);

    g_x[b * XD + d]        = uv;
    g_x[b * XD + 128 + d]  = itv;
    g_x[b * XD + 256 + d]  = acc / cnt;
}

// grid 32 x block 384: block g reduces batches [g*128, g*128+128)
__global__ void stats_kernel() {
    int f = threadIdx.x;
    int base = blockIdx.x * 128;
    float s = 0.f, s2 = 0.f;
    #pragma unroll 4
    for (int i = 0; i < 128; i++) {
        float v = g_x[(base + i) * XD + f];
        s += v; s2 += v * v;
    }
    atomicAdd(&g_sum[f], s);
    atomicAdd(&g_sumsq[f], s2);
}

__global__ void finalize_kernel(const float* __restrict__ gamma,
                                const float* __restrict__ beta) {
    int f = threadIdx.x;
    const float invN = 1.f / (float)BATCH;
    float mean = g_sum[f] * invN;
    float var  = g_sumsq[f] * invN - mean * mean;
    float inv  = rsqrtf(var + BN_EPS);
    float sc   = gamma[f] * inv;
    g_scale[f] = sc;
    g_shift[f] = beta[f] - mean * sc;
}

// y1 = prelu(BN(x) @ W1^T + b1)   M=4096 N=200 K=384
// BM=64 BN=64 BK=16, 256 threads, 4x4 per thread
__global__ void gemm1_kernel(const float* __restrict__ W1,
                             const float* __restrict__ b1,
                             const float* __restrict__ a1) {
    __shared__ float As[16][68];
    __shared__ float Bs[16][68];
    int m0 = blockIdx.x * 64;
    int n0 = blockIdx.y * 64;
    int tid = threadIdx.x;
    int tx = tid & 15, ty = tid >> 4;
    int lk = tid & 15, lr = tid >> 4;

    float acc[4][4];
    #pragma unroll
    for (int i = 0; i < 4; i++)
        #pragma unroll
        for (int j = 0; j < 4; j++) acc[i][j] = 0.f;

    for (int k0 = 0; k0 < XD; k0 += 16) {
        float sc = g_scale[k0 + lk], sh = g_shift[k0 + lk];
        #pragma unroll
        for (int i = 0; i < 4; i++) {
            int m = lr + 16 * i;
            As[lk][m] = g_x[(m0 + m) * XD + k0 + lk] * sc + sh;
        }
        #pragma unroll
        for (int i = 0; i < 4; i++) {
            int nn = lr + 16 * i;
            int gn = n0 + nn;
            Bs[lk][nn] = (gn < H1) ? W1[gn * XD + k0 + lk] : 0.f;
        }
        __syncthreads();
        #pragma unroll
        for (int kk = 0; kk < 16; kk++) {
            float a[4], bb[4];
            #pragma unroll
            for (int i = 0; i < 4; i++) a[i] = As[kk][ty * 4 + i];
            #pragma unroll
            for (int j = 0; j < 4; j++) bb[j] = Bs[kk][tx * 4 + j];
            #pragma unroll
            for (int i = 0; i < 4; i++)
                #pragma unroll
                for (int j = 0; j < 4; j++) acc[i][j] += a[i] * bb[j];
        }
        __syncthreads();
    }
    float alpha = a1[0];
    #pragma unroll
    for (int i = 0; i < 4; i++) {
        int gm = m0 + ty * 4 + i;
        #pragma unroll
        for (int j = 0; j < 4; j++) {
            int gn = n0 + tx * 4 + j;
            if (gn < H1) {
                float v = acc[i][j] + b1[gn];
                v = (v >= 0.f) ? v : alpha * v;
                g_y1[gm * H1 + gn] = v;
            }
        }
    }
}

// y2 = prelu(y1 @ W2^T + b2)   M=4096 N=80 K=200
// BM=64 BN=80 BK=8, 256 threads, 4x5 per thread
__global__ void gemm2_kernel(const float* __restrict__ W2,
                             const float* __restrict__ b2,
                             const float* __restrict__ a2) {
    __shared__ float As[8][68];
    __shared__ float Bs[8][84];
    int m0 = blockIdx.x * 64;
    int tid = threadIdx.x;
    int tx = tid & 15, ty = tid >> 4;   // tx -> n (5 each), ty -> m (4 each)
    int lk = tid & 7, lr = tid >> 3;    // loader mapping for A

    float acc[4][5];
    #pragma unroll
    for (int i = 0; i < 4; i++)
        #pragma unroll
        for (int j = 0; j < 5; j++) acc[i][j] = 0.f;

    for (int k0 = 0; k0 < H1; k0 += 8) {
        As[lk][lr]      = g_y1[(m0 + lr) * H1 + k0 + lk];
        As[lk][lr + 32] = g_y1[(m0 + lr + 32) * H1 + k0 + lk];
        for (int i = tid; i < 640; i += 256) {
            int bk = i & 7, bn = i >> 3;
            Bs[bk][bn] = W2[bn * H1 + k0 + bk];
        }
        __syncthreads();
        #pragma unroll
        for (int kk = 0; kk < 8; kk++) {
            float a[4], bb[5];
            #pragma unroll
            for (int i = 0; i < 4; i++) a[i] = As[kk][ty * 4 + i];
            #pragma unroll
            for (int j = 0; j < 5; j++) bb[j] = Bs[kk][tx * 5 + j];
            #pragma unroll
            for (int i = 0; i < 4; i++)
                #pragma unroll
                for (int j = 0; j < 5; j++) acc[i][j] += a[i] * bb[j];
        }
        __syncthreads();
    }
    float alpha = a2[0];
    #pragma unroll
    for (int i = 0; i < 4; i++) {
        int gm = m0 + ty * 4 + i;
        #pragma unroll
        for (int j = 0; j < 5; j++) {
            int gn = tx * 5 + j;
            float v = acc[i][j] + b2[gn];
            v = (v >= 0.f) ? v : alpha * v;
            g_y2[gm * H2 + gn] = v;
        }
    }
}

// logits = y2 @ W3^T + b3, softmax over 2; one warp per row
__global__ void out_kernel(const float* __restrict__ W3,
                           const float* __restrict__ b3,
                           float* __restrict__ out) {
    int gid = blockIdx.x * blockDim.x + threadIdx.x;
    int warp = gid >> 5, lane = gid & 31;
    if (warp >= BATCH) return;
    const float* row = g_y2 + warp * H2;
    float s0 = 0.f, s1 = 0.f;
    #pragma unroll
    for (int k = lane; k < H2; k += 32) {
        float v = row[k];
        s0 += v * W3[k];
        s1 += v * W3[H2 + k];
    }
    #pragma unroll
    for (int off = 16; off; off >>= 1) {
        s0 += __shfl_down_sync(0xffffffffu, s0, off);
        s1 += __shfl_down_sync(0xffffffffu, s1, off);
    }
    if (lane == 0) {
        float l0 = s0 + b3[0], l1 = s1 + b3[1];
        float m = fmaxf(l0, l1);
        float e0 = expf(l0 - m), e1 = expf(l1 - m);
        float inv = 1.f / (e0 + e1);
        out[warp * 2 + 0] = e0 * inv;
        out[warp * 2 + 1] = e1 * inv;
    }
}

// ---------------- launch ----------------
extern "C" void kernel_launch(void* const* d_in, const int* in_sizes, int n_in,
                              void* d_out, int out_size) {
    const int*   user      = (const int*)d_in[0];
    const int*   item      = (const int*)d_in[1];
    const int*   history   = (const int*)d_in[2];
    // d_in[3] = length (unused; reference semantics derived from history zeros)
    const int*   cate_list = (const int*)d_in[4];
    const float* uW        = (const float*)d_in[5];
    const float* iW        = (const float*)d_in[6];
    const float* cW        = (const float*)d_in[7];
    const float* gamma     = (const float*)d_in[8];
    const float* beta      = (const float*)d_in[9];
    const float* W1        = (const float*)d_in[10];
    const float* b1        = (const float*)d_in[11];
    const float* a1        = (const float*)d_in[12];
    const float* W2        = (const float*)d_in[13];
    const float* b2        = (const float*)d_in[14];
    const float* a2        = (const float*)d_in[15];
    const float* W3        = (const float*)d_in[16];
    const float* b3        = (const float*)d_in[17];
    float* out = (float*)d_out;

    init_kernel<<<1, 384>>>();
    scan_kernel<<<16, 256>>>(history);
    embed_kernel<<<BATCH, 128>>>(user, item, history, cate_list, uW, iW, cW);
    stats_kernel<<<32, 384>>>();
    finalize_kernel<<<1, 384>>>(gamma, beta);
    dim3 g1(BATCH / 64, 4);
    gemm1_kernel<<<g1, 256>>>(W1, b1, a1);
    gemm2_kernel<<<BATCH / 64, 256>>>(W2, b2, a2);
    out_kernel<<<BATCH / 8, 256>>>(W3, b3, out);
}

// round 4
// speedup vs baseline: 1.0853x; 1.0853x over previous
#include <cuda_runtime.h>
#include <math.h>

#define BATCH 4096
#define HLEN  200
#define XD    384
#define H1    200
#define H2    80
#define BN_EPS 1e-5f
#define RPB   8      // rows per embed CTA

// ---------------- device scratch (static allocation only) ----------------
__device__ float g_x[BATCH * XD];     // concat(u, it, pooled)
__device__ float g_y1[BATCH * H1];
__device__ float g_sum[XD];           // zero-initialized; finalize resets after use
__device__ float g_sumsq[XD];
__device__ float g_scale[XD];
__device__ float g_shift[XD];
__device__ int   g_first_inactive = BATCH;  // finalize resets after use

// ---------------- kernels ----------------

// outer-break semantics: first row b with history[b,0]==0 deactivates rows >= b
__global__ void scan_kernel(const int* __restrict__ history) {
    int b = blockIdx.x * blockDim.x + threadIdx.x;
    if (b < BATCH && history[b * HLEN] == 0) atomicMin(&g_first_inactive, b);
}

// warp-per-row embedding gather + pool, fused BN partial sums.
// 256 threads = 8 warps = 8 rows per CTA. Lane k (k<16) covers item dims
// [4k,4k+4); lane 16+k covers cate dims [4k,4k+4) — one LDG.128 per (row,l).
__global__ void embed_kernel(const int* __restrict__ user,
                             const int* __restrict__ item,
                             const int* __restrict__ history,
                             const int* __restrict__ cate_list,
                             const float* __restrict__ uW,   // [100000,128]
                             const float* __restrict__ iW,   // [100000,64]
                             const float* __restrict__ cW) { // [1000,64]
    __shared__ int   ids[RPB][HLEN];
    __shared__ float sx[RPB][XD];     // per-row x values for BN reduction

    int b0  = blockIdx.x * RPB;
    int tid = threadIdx.x;

    for (int i = tid; i < RPB * HLEN; i += 256)
        ids[i / HLEN][i % HLEN] = history[b0 * HLEN + i];
    __syncthreads();

    int w = tid >> 5, lane = tid & 31;
    int b = b0 + w;

    // first-zero prefix length via ballot over 32-chunks
    int n = HLEN;
    #pragma unroll
    for (int c = 0; c < (HLEN + 31) / 32; c++) {
        int idx = c * 32 + lane;
        int v = (idx < HLEN) ? ids[w][idx] : 1;
        unsigned m = __ballot_sync(0xffffffffu, v == 0);
        if (m) { n = c * 32 + __ffs(m) - 1; break; }
    }

    int ne = (b < g_first_inactive) ? n : 0;
    float inv_cnt = 1.0f / (float)(ne > 0 ? ne : 1);

    int half = lane >> 4;           // 0 = item half, 1 = cate half
    int q    = lane & 15;           // float4 index within the 64-dim half
    const float4* iW4 = (const float4*)iW;
    const float4* cW4 = (const float4*)cW;

    float4 acc = make_float4(0.f, 0.f, 0.f, 0.f);
    #pragma unroll 4
    for (int l = 0; l < ne; l++) {
        int id  = ids[w][l];
        int rid = half ? __ldg(&cate_list[id]) : id;
        const float4* tab = half ? cW4 : iW4;
        float4 v = __ldg(&tab[rid * 16 + q]);
        acc.x += v.x; acc.y += v.y; acc.z += v.z; acc.w += v.w;
    }
    float4 p = make_float4(acc.x * inv_cnt, acc.y * inv_cnt,
                           acc.z * inv_cnt, acc.w * inv_cnt);

    // user + item embeddings
    float4 uv = __ldg(&((const float4*)uW)[user[b] * 32 + lane]);
    int iid  = item[b];
    int rid2 = half ? __ldg(&cate_list[iid]) : iid;
    const float4* tab2 = half ? cW4 : iW4;
    float4 itv = __ldg(&tab2[rid2 * 16 + q]);

    // write x and stage for BN reduction
    float4* xr = (float4*)&g_x[b * XD];
    xr[lane]      = uv;
    xr[32 + lane] = itv;
    xr[64 + lane] = p;
    float4* sxr = (float4*)sx[w];
    sxr[lane]      = uv;
    sxr[32 + lane] = itv;
    sxr[64 + lane] = p;
    __syncthreads();

    // per-CTA reduce over 8 rows, then RED.ADD to global BN accumulators
    for (int f = tid; f < XD; f += 256) {
        float s1 = 0.f, s2 = 0.f;
        #pragma unroll
        for (int r = 0; r < RPB; r++) {
            float v = sx[r][f];
            s1 += v; s2 += v * v;
        }
        atomicAdd(&g_sum[f], s1);
        atomicAdd(&g_sumsq[f], s2);
    }
}

// compute BN scale/shift and self-reset accumulators for the next replay
__global__ void finalize_kernel(const float* __restrict__ gamma,
                                const float* __restrict__ beta) {
    int f = threadIdx.x;
    const float invN = 1.f / (float)BATCH;
    float mean = g_sum[f] * invN;
    float var  = g_sumsq[f] * invN - mean * mean;
    float inv  = rsqrtf(var + BN_EPS);
    float sc   = gamma[f] * inv;
    g_scale[f] = sc;
    g_shift[f] = beta[f] - mean * sc;
    g_sum[f]   = 0.f;
    g_sumsq[f] = 0.f;
    if (f == 0) g_first_inactive = BATCH;
}

// y1 = prelu(BN(x) @ W1^T + b1)   M=4096 N=200(pad 256) K=384
// BM=128 BN=64 BK=16, 256 threads, 8x4 per thread
__global__ void gemm1_kernel(const float* __restrict__ W1,
                             const float* __restrict__ b1,
                             const float* __restrict__ a1p) {
    __shared__ float As[16][132];
    __shared__ float Bs[16][68];
    __shared__ float ss[XD], sh[XD];

    int m0 = blockIdx.x * 128;
    int n0 = blockIdx.y * 64;
    int tid = threadIdx.x;
    int tx = tid & 15, ty = tid >> 4;

    for (int i = tid; i < XD; i += 256) { ss[i] = g_scale[i]; sh[i] = g_shift[i]; }

    float acc[8][4];
    #pragma unroll
    for (int i = 0; i < 8; i++)
        #pragma unroll
        for (int j = 0; j < 4; j++) acc[i][j] = 0.f;
    __syncthreads();

    for (int k0 = 0; k0 < XD; k0 += 16) {
        #pragma unroll
        for (int u2 = 0; u2 < 2; u2++) {
            int i = tid + u2 * 256;
            int m = i >> 2, kq = (i & 3) * 4;
            float4 v = *(const float4*)&g_x[(m0 + m) * XD + k0 + kq];
            As[kq + 0][m] = v.x * ss[k0 + kq + 0] + sh[k0 + kq + 0];
            As[kq + 1][m] = v.y * ss[k0 + kq + 1] + sh[k0 + kq + 1];
            As[kq + 2][m] = v.z * ss[k0 + kq + 2] + sh[k0 + kq + 2];
            As[kq + 3][m] = v.w * ss[k0 + kq + 3] + sh[k0 + kq + 3];
        }
        {
            int nn = tid >> 2, kq = (tid & 3) * 4;
            int gn = n0 + nn;
            float4 v = (gn < H1) ? *(const float4*)&W1[gn * XD + k0 + kq]
                                 : make_float4(0.f, 0.f, 0.f, 0.f);
            Bs[kq + 0][nn] = v.x; Bs[kq + 1][nn] = v.y;
            Bs[kq + 2][nn] = v.z; Bs[kq + 3][nn] = v.w;
        }
        __syncthreads();
        #pragma unroll
        for (int kk = 0; kk < 16; kk++) {
            float a[8], bb[4];
            float4 t0 = *(const float4*)&As[kk][ty * 8];
            float4 t1 = *(const float4*)&As[kk][ty * 8 + 4];
            a[0]=t0.x; a[1]=t0.y; a[2]=t0.z; a[3]=t0.w;
            a[4]=t1.x; a[5]=t1.y; a[6]=t1.z; a[7]=t1.w;
            float4 tb = *(const float4*)&Bs[kk][tx * 4];
            bb[0]=tb.x; bb[1]=tb.y; bb[2]=tb.z; bb[3]=tb.w;
            #pragma unroll
            for (int i = 0; i < 8; i++)
                #pragma unroll
                for (int j = 0; j < 4; j++) acc[i][j] += a[i] * bb[j];
        }
        __syncthreads();
    }
    float alpha = a1p[0];
    #pragma unroll
    for (int i = 0; i < 8; i++) {
        int gm = m0 + ty * 8 + i;
        #pragma unroll
        for (int j = 0; j < 4; j++) {
            int gn = n0 + tx * 4 + j;
            if (gn < H1) {
                float v = acc[i][j] + b1[gn];
                v = (v >= 0.f) ? v : alpha * v;
                g_y1[gm * H1 + gn] = v;
            }
        }
    }
}

// y2 = prelu(y1 @ W2^T + b2); logits = y2 @ W3^T + b3; softmax — fused.
// M=4096 N=80 K=200; BM=64 BN=80 BK=8, 256 threads, 4x5 per thread
__global__ void gemm2_out_kernel(const float* __restrict__ W2,
                                 const float* __restrict__ b2,
                                 const float* __restrict__ a2p,
                                 const float* __restrict__ W3,
                                 const float* __restrict__ b3,
                                 float* __restrict__ out) {
    __shared__ float As[8][68];
    __shared__ float Bs[8][84];
    __shared__ float sy[64][81];
    __shared__ float sw3[2 * H2];

    int m0 = blockIdx.x * 64;
    int tid = threadIdx.x;
    int tx = tid & 15, ty = tid >> 4;     // tx -> n (5 each), ty -> m (4 each)
    int lk2 = tid & 3, lm = tid >> 2;     // A-loader: float2 along k

    if (tid < 2 * H2) sw3[tid] = W3[tid];

    float acc[4][5];
    #pragma unroll
    for (int i = 0; i < 4; i++)
        #pragma unroll
        for (int j = 0; j < 5; j++) acc[i][j] = 0.f;

    for (int k0 = 0; k0 < H1; k0 += 8) {
        float2 va = *(const float2*)&g_y1[(m0 + lm) * H1 + k0 + lk2 * 2];
        As[lk2 * 2 + 0][lm] = va.x;
        As[lk2 * 2 + 1][lm] = va.y;
        for (int i = tid; i < 8 * H2; i += 256) {
            int bk = i & 7, bn = i >> 3;
            Bs[bk][bn] = W2[bn * H1 + k0 + bk];
        }
        __syncthreads();
        #pragma unroll
        for (int kk = 0; kk < 8; kk++) {
            float a[4], bb[5];
            float4 ta = *(const float4*)&As[kk][ty * 4];
            a[0]=ta.x; a[1]=ta.y; a[2]=ta.z; a[3]=ta.w;
            #pragma unroll
            for (int j = 0; j < 5; j++) bb[j] = Bs[kk][tx * 5 + j];
            #pragma unroll
            for (int i = 0; i < 4; i++)
                #pragma unroll
                for (int j = 0; j < 5; j++) acc[i][j] += a[i] * bb[j];
        }
        __syncthreads();
    }

    float alpha = a2p[0];
    #pragma unroll
    for (int i = 0; i < 4; i++)
        #pragma unroll
        for (int j = 0; j < 5; j++) {
            float v = acc[i][j] + b2[tx * 5 + j];
            v = (v >= 0.f) ? v : alpha * v;
            sy[ty * 4 + i][tx * 5 + j] = v;
        }
    __syncthreads();

    // logits + softmax: 4 threads per row, 20 dims each, shuffle-combine
    int row = tid >> 2, part = tid & 3;
    float s0 = 0.f, s1 = 0.f;
    int kbase = part * 20;
    #pragma unroll
    for (int k = 0; k < 20; k++) {
        float v = sy[row][kbase + k];
        s0 += v * sw3[kbase + k];
        s1 += v * sw3[H2 + kbase + k];
    }
    s0 += __shfl_down_sync(0xffffffffu, s0, 2, 4);
    s0 += __shfl_down_sync(0xffffffffu, s0, 1, 4);
    s1 += __shfl_down_sync(0xffffffffu, s1, 2, 4);
    s1 += __shfl_down_sync(0xffffffffu, s1, 1, 4);
    if (part == 0) {
        float l0 = s0 + b3[0], l1 = s1 + b3[1];
        float m = fmaxf(l0, l1);
        float e0 = expf(l0 - m), e1 = expf(l1 - m);
        float inv = 1.f / (e0 + e1);
        out[(m0 + row) * 2 + 0] = e0 * inv;
        out[(m0 + row) * 2 + 1] = e1 * inv;
    }
}

// ---------------- launch ----------------
extern "C" void kernel_launch(void* const* d_in, const int* in_sizes, int n_in,
                              void* d_out, int out_size) {
    const int*   user      = (const int*)d_in[0];
    const int*   item      = (const int*)d_in[1];
    const int*   history   = (const int*)d_in[2];
    // d_in[3] = length (unused; semantics derived from history zeros)
    const int*   cate_list = (const int*)d_in[4];
    const float* uW        = (const float*)d_in[5];
    const float* iW        = (const float*)d_in[6];
    const float* cW        = (const float*)d_in[7];
    const float* gamma     = (const float*)d_in[8];
    const float* beta      = (const float*)d_in[9];
    const float* W1        = (const float*)d_in[10];
    const float* b1        = (const float*)d_in[11];
    const float* a1        = (const float*)d_in[12];
    const float* W2        = (const float*)d_in[13];
    const float* b2        = (const float*)d_in[14];
    const float* a2        = (const float*)d_in[15];
    const float* W3        = (const float*)d_in[16];
    const float* b3        = (const float*)d_in[17];
    float* out = (float*)d_out;

    scan_kernel<<<16, 256>>>(history);
    embed_kernel<<<BATCH / RPB, 256>>>(user, item, history, cate_list, uW, iW, cW);
    finalize_kernel<<<1, 384>>>(gamma, beta);
    dim3 g1(BATCH / 128, 4);
    gemm1_kernel<<<g1, 256>>>(W1, b1, a1);
    gemm2_out_kernel<<<BATCH / 64, 256>>>(W2, b2, a2, W3, b3, out);
}

// round 5
// speedup vs baseline: 1.2508x; 1.1525x over previous
#include <cuda_runtime.h>
#include <math.h>

#define BATCH 4096
#define HLEN  200
#define XD    384
#define H1    200
#define H2    80
#define BN_EPS 1e-5f
#define RPB   8      // rows per embed CTA

// ---------------- device scratch (static allocation only) ----------------
__device__ float g_x[BATCH * XD];     // concat(u, it, pooled)
__device__ float g_y1[BATCH * H1];
__device__ float g_sum[XD];           // zero-initialized; finalize resets after use
__device__ float g_sumsq[XD];
__device__ float g_scale[XD];
__device__ float g_shift[XD];
__device__ int   g_first_inactive = BATCH;  // finalize resets after use

// ---------------- kernels ----------------

// outer-break semantics: first row b with history[b,0]==0 deactivates rows >= b
__global__ void scan_kernel(const int* __restrict__ history) {
    int b = blockIdx.x * blockDim.x + threadIdx.x;
    if (b < BATCH && history[b * HLEN] == 0) atomicMin(&g_first_inactive, b);
}

// warp-per-row embedding gather + pool, fused BN partial sums.
__global__ void embed_kernel(const int* __restrict__ user,
                             const int* __restrict__ item,
                             const int* __restrict__ history,
                             const int* __restrict__ cate_list,
                             const float* __restrict__ uW,   // [100000,128]
                             const float* __restrict__ iW,   // [100000,64]
                             const float* __restrict__ cW) { // [1000,64]
    __shared__ int   ids[RPB][HLEN];
    __shared__ float sx[RPB][XD];     // per-row x values for BN reduction

    int b0  = blockIdx.x * RPB;
    int tid = threadIdx.x;

    for (int i = tid; i < RPB * HLEN; i += 256)
        ids[i / HLEN][i % HLEN] = history[b0 * HLEN + i];
    __syncthreads();

    int w = tid >> 5, lane = tid & 31;
    int b = b0 + w;

    // first-zero prefix length via ballot over 32-chunks
    int n = HLEN;
    #pragma unroll
    for (int c = 0; c < (HLEN + 31) / 32; c++) {
        int idx = c * 32 + lane;
        int v = (idx < HLEN) ? ids[w][idx] : 1;
        unsigned m = __ballot_sync(0xffffffffu, v == 0);
        if (m) { n = c * 32 + __ffs(m) - 1; break; }
    }

    int ne = (b < g_first_inactive) ? n : 0;
    float inv_cnt = 1.0f / (float)(ne > 0 ? ne : 1);

    int half = lane >> 4;           // 0 = item half, 1 = cate half
    int q    = lane & 15;           // float4 index within the 64-dim half
    const float4* iW4 = (const float4*)iW;
    const float4* cW4 = (const float4*)cW;

    float4 acc = make_float4(0.f, 0.f, 0.f, 0.f);
    #pragma unroll 8
    for (int l = 0; l < ne; l++) {
        int id  = ids[w][l];
        int rid = half ? __ldg(&cate_list[id]) : id;
        const float4* tab = half ? cW4 : iW4;
        float4 v = __ldg(&tab[rid * 16 + q]);
        acc.x += v.x; acc.y += v.y; acc.z += v.z; acc.w += v.w;
    }
    float4 p = make_float4(acc.x * inv_cnt, acc.y * inv_cnt,
                           acc.z * inv_cnt, acc.w * inv_cnt);

    // user + item embeddings
    float4 uv = __ldg(&((const float4*)uW)[user[b] * 32 + lane]);
    int iid  = item[b];
    int rid2 = half ? __ldg(&cate_list[iid]) : iid;
    const float4* tab2 = half ? cW4 : iW4;
    float4 itv = __ldg(&tab2[rid2 * 16 + q]);

    float4* xr = (float4*)&g_x[b * XD];
    xr[lane]      = uv;
    xr[32 + lane] = itv;
    xr[64 + lane] = p;
    float4* sxr = (float4*)sx[w];
    sxr[lane]      = uv;
    sxr[32 + lane] = itv;
    sxr[64 + lane] = p;
    __syncthreads();

    // per-CTA reduce over 8 rows, then RED.ADD to global BN accumulators
    for (int f = tid; f < XD; f += 256) {
        float s1 = 0.f, s2 = 0.f;
        #pragma unroll
        for (int r = 0; r < RPB; r++) {
            float v = sx[r][f];
            s1 += v; s2 += v * v;
        }
        atomicAdd(&g_sum[f], s1);
        atomicAdd(&g_sumsq[f], s2);
    }
}

// compute BN scale/shift and self-reset accumulators for the next replay
__global__ void finalize_kernel(const float* __restrict__ gamma,
                                const float* __restrict__ beta) {
    int f = threadIdx.x;
    const float invN = 1.f / (float)BATCH;
    float mean = g_sum[f] * invN;
    float var  = g_sumsq[f] * invN - mean * mean;
    float inv  = rsqrtf(var + BN_EPS);
    float sc   = gamma[f] * inv;
    g_scale[f] = sc;
    g_shift[f] = beta[f] - mean * sc;
    g_sum[f]   = 0.f;
    g_sumsq[f] = 0.f;
    if (f == 0) g_first_inactive = BATCH;
}

// y1 = prelu(BN(x) @ W1^T + b1)   M=4096 N=200(pad 256) K=384
// BM=128 BN=64 BK=16, 256 threads, 8x4 per thread.
// Double-buffered smem, reg prefetch, one barrier per K-iter.
// tx = tid>>4 so n-columns are half-warp-uniform -> dead warps in the
// last n-block (cols 200..255) skip the FMA loop entirely.
__global__ void gemm1_kernel(const float* __restrict__ W1,
                             const float* __restrict__ b1,
                             const float* __restrict__ a1p) {
    __shared__ float As[2][16][132];
    __shared__ float Bs[2][16][68];
    __shared__ float ss[XD], sh[XD];

    int m0 = blockIdx.x * 128;
    int n0 = blockIdx.y * 64;
    int tid = threadIdx.x;
    int tx = tid >> 4;        // 0..15 -> n-group (4 cols each)
    int ty = tid & 15;        // 0..15 -> m-group (8 rows each)
    bool nactive = (n0 + tx * 4) < H1;

    // cooperative-loader indices
    int lmA0 = tid >> 2;                 // rows 0..63   (i = tid)
    int lmA1 = (tid + 256) >> 2;         // rows 64..127 (i = tid+256)
    int lkq  = (tid & 3) * 4;            // k-quad within BK
    int lnB  = tid >> 2;                 // 0..63 n within tile
    int gnB  = n0 + lnB;

    for (int i = tid; i < XD; i += 256) { ss[i] = g_scale[i]; sh[i] = g_shift[i]; }

    float acc[8][4];
    #pragma unroll
    for (int i = 0; i < 8; i++)
        #pragma unroll
        for (int j = 0; j < 4; j++) acc[i][j] = 0.f;

    // prologue: tile 0 -> regs -> smem buf 0
    float4 pa0 = *(const float4*)&g_x[(m0 + lmA0) * XD + lkq];
    float4 pa1 = *(const float4*)&g_x[(m0 + lmA1) * XD + lkq];
    float4 pb  = (gnB < H1) ? *(const float4*)&W1[gnB * XD + lkq]
                            : make_float4(0.f, 0.f, 0.f, 0.f);
    __syncthreads();   // ss/sh ready
    {
        As[0][lkq + 0][lmA0] = pa0.x * ss[lkq + 0] + sh[lkq + 0];
        As[0][lkq + 1][lmA0] = pa0.y * ss[lkq + 1] + sh[lkq + 1];
        As[0][lkq + 2][lmA0] = pa0.z * ss[lkq + 2] + sh[lkq + 2];
        As[0][lkq + 3][lmA0] = pa0.w * ss[lkq + 3] + sh[lkq + 3];
        As[0][lkq + 0][lmA1] = pa1.x * ss[lkq + 0] + sh[lkq + 0];
        As[0][lkq + 1][lmA1] = pa1.y * ss[lkq + 1] + sh[lkq + 1];
        As[0][lkq + 2][lmA1] = pa1.z * ss[lkq + 2] + sh[lkq + 2];
        As[0][lkq + 3][lmA1] = pa1.w * ss[lkq + 3] + sh[lkq + 3];
        Bs[0][lkq + 0][lnB] = pb.x;
        Bs[0][lkq + 1][lnB] = pb.y;
        Bs[0][lkq + 2][lnB] = pb.z;
        Bs[0][lkq + 3][lnB] = pb.w;
    }
    __syncthreads();

    #pragma unroll 1
    for (int it = 0; it < 24; it++) {
        int cur = it & 1;
        float4 na0, na1, nb;
        int k0n = (it + 1) * 16;
        if (it < 23) {
            na0 = *(const float4*)&g_x[(m0 + lmA0) * XD + k0n + lkq];
            na1 = *(const float4*)&g_x[(m0 + lmA1) * XD + k0n + lkq];
            nb  = (gnB < H1) ? *(const float4*)&W1[gnB * XD + k0n + lkq]
                             : make_float4(0.f, 0.f, 0.f, 0.f);
        }
        if (nactive) {
            #pragma unroll
            for (int kk = 0; kk < 16; kk++) {
                float4 t0 = *(const float4*)&As[cur][kk][ty * 8];
                float4 t1 = *(const float4*)&As[cur][kk][ty * 8 + 4];
                float4 tb = *(const float4*)&Bs[cur][kk][tx * 4];
                float a[8] = {t0.x, t0.y, t0.z, t0.w, t1.x, t1.y, t1.z, t1.w};
                float bb[4] = {tb.x, tb.y, tb.z, tb.w};
                #pragma unroll
                for (int i = 0; i < 8; i++)
                    #pragma unroll
                    for (int j = 0; j < 4; j++) acc[i][j] += a[i] * bb[j];
            }
        }
        if (it < 23) {
            int nxt = cur ^ 1;
            As[nxt][lkq + 0][lmA0] = na0.x * ss[k0n + lkq + 0] + sh[k0n + lkq + 0];
            As[nxt][lkq + 1][lmA0] = na0.y * ss[k0n + lkq + 1] + sh[k0n + lkq + 1];
            As[nxt][lkq + 2][lmA0] = na0.z * ss[k0n + lkq + 2] + sh[k0n + lkq + 2];
            As[nxt][lkq + 3][lmA0] = na0.w * ss[k0n + lkq + 3] + sh[k0n + lkq + 3];
            As[nxt][lkq + 0][lmA1] = na1.x * ss[k0n + lkq + 0] + sh[k0n + lkq + 0];
            As[nxt][lkq + 1][lmA1] = na1.y * ss[k0n + lkq + 1] + sh[k0n + lkq + 1];
            As[nxt][lkq + 2][lmA1] = na1.z * ss[k0n + lkq + 2] + sh[k0n + lkq + 2];
            As[nxt][lkq + 3][lmA1] = na1.w * ss[k0n + lkq + 3] + sh[k0n + lkq + 3];
            Bs[nxt][lkq + 0][lnB] = nb.x;
            Bs[nxt][lkq + 1][lnB] = nb.y;
            Bs[nxt][lkq + 2][lnB] = nb.z;
            Bs[nxt][lkq + 3][lnB] = nb.w;
        }
        __syncthreads();
    }

    if (nactive) {
        float alpha = a1p[0];
        #pragma unroll
        for (int j = 0; j < 4; j++) {
            int gn = n0 + tx * 4 + j;
            if (gn < H1) {
                float bias = b1[gn];
                #pragma unroll
                for (int i = 0; i < 8; i++) {
                    int gm = m0 + ty * 8 + i;
                    float v = acc[i][j] + bias;
                    v = (v >= 0.f) ? v : alpha * v;
                    g_y1[gm * H1 + gn] = v;
                }
            }
        }
    }
}

// y2 = prelu(y1 @ W2^T + b2); logits = y2 @ W3^T + b3; softmax — fused.
// M=4096 N=80 K=200; BM=64 BN=80 BK=8, 256 threads, 4x5, double-buffered.
__global__ void gemm2_out_kernel(const float* __restrict__ W2,
                                 const float* __restrict__ b2,
                                 const float* __restrict__ a2p,
                                 const float* __restrict__ W3,
                                 const float* __restrict__ b3,
                                 float* __restrict__ out) {
    __shared__ float As[2][8][68];
    __shared__ float Bs[2][8][84];
    __shared__ float sy[64][81];
    __shared__ float sw3[2 * H2];

    int m0 = blockIdx.x * 64;
    int tid = threadIdx.x;
    int tx = tid & 15, ty = tid >> 4;     // tx -> n (5 each), ty -> m (4 each)
    int lk2 = (tid & 3) * 2, lm = tid >> 2;       // A loader: float2 along k
    int bn = tid >> 1, bq = (tid & 1) * 4;        // B loader: threads<160 load float4

    if (tid < 2 * H2) sw3[tid] = W3[tid];

    float acc[4][5];
    #pragma unroll
    for (int i = 0; i < 4; i++)
        #pragma unroll
        for (int j = 0; j < 5; j++) acc[i][j] = 0.f;

    // prologue
    float2 pa = *(const float2*)&g_y1[(m0 + lm) * H1 + lk2];
    float4 pb = (tid < 160) ? *(const float4*)&W2[bn * H1 + bq]
                            : make_float4(0.f, 0.f, 0.f, 0.f);
    As[0][lk2 + 0][lm] = pa.x;
    As[0][lk2 + 1][lm] = pa.y;
    if (tid < 160) {
        Bs[0][bq + 0][bn] = pb.x; Bs[0][bq + 1][bn] = pb.y;
        Bs[0][bq + 2][bn] = pb.z; Bs[0][bq + 3][bn] = pb.w;
    }
    __syncthreads();

    #pragma unroll 1
    for (int it = 0; it < 25; it++) {
        int cur = it & 1;
        float2 na; float4 nb;
        int k0n = (it + 1) * 8;
        if (it < 24) {
            na = *(const float2*)&g_y1[(m0 + lm) * H1 + k0n + lk2];
            if (tid < 160) nb = *(const float4*)&W2[bn * H1 + k0n + bq];
        }
        #pragma unroll
        for (int kk = 0; kk < 8; kk++) {
            float4 ta = *(const float4*)&As[cur][kk][ty * 4];
            float a[4] = {ta.x, ta.y, ta.z, ta.w};
            float bb[5];
            #pragma unroll
            for (int j = 0; j < 5; j++) bb[j] = Bs[cur][kk][tx * 5 + j];
            #pragma unroll
            for (int i = 0; i < 4; i++)
                #pragma unroll
                for (int j = 0; j < 5; j++) acc[i][j] += a[i] * bb[j];
        }
        if (it < 24) {
            int nxt = cur ^ 1;
            As[nxt][lk2 + 0][lm] = na.x;
            As[nxt][lk2 + 1][lm] = na.y;
            if (tid < 160) {
                Bs[nxt][bq + 0][bn] = nb.x; Bs[nxt][bq + 1][bn] = nb.y;
                Bs[nxt][bq + 2][bn] = nb.z; Bs[nxt][bq + 3][bn] = nb.w;
            }
        }
        __syncthreads();
    }

    float alpha = a2p[0];
    #pragma unroll
    for (int i = 0; i < 4; i++)
        #pragma unroll
        for (int j = 0; j < 5; j++) {
            float v = acc[i][j] + b2[tx * 5 + j];
            v = (v >= 0.f) ? v : alpha * v;
            sy[ty * 4 + i][tx * 5 + j] = v;
        }
    __syncthreads();

    // logits + softmax: 4 threads per row, 20 dims each, shuffle-combine
    int row = tid >> 2, part = tid & 3;
    float s0 = 0.f, s1 = 0.f;
    int kbase = part * 20;
    #pragma unroll
    for (int k = 0; k < 20; k++) {
        float v = sy[row][kbase + k];
        s0 += v * sw3[kbase + k];
        s1 += v * sw3[H2 + kbase + k];
    }
    s0 += __shfl_down_sync(0xffffffffu, s0, 2, 4);
    s0 += __shfl_down_sync(0xffffffffu, s0, 1, 4);
    s1 += __shfl_down_sync(0xffffffffu, s1, 2, 4);
    s1 += __shfl_down_sync(0xffffffffu, s1, 1, 4);
    if (part == 0) {
        float l0 = s0 + b3[0], l1 = s1 + b3[1];
        float m = fmaxf(l0, l1);
        float e0 = expf(l0 - m), e1 = expf(l1 - m);
        float inv = 1.f / (e0 + e1);
        out[(m0 + row) * 2 + 0] = e0 * inv;
        out[(m0 + row) * 2 + 1] = e1 * inv;
    }
}

// ---------------- launch ----------------
extern "C" void kernel_launch(void* const* d_in, const int* in_sizes, int n_in,
                              void* d_out, int out_size) {
    const int*   user      = (const int*)d_in[0];
    const int*   item      = (const int*)d_in[1];
    const int*   history   = (const int*)d_in[2];
    // d_in[3] = length (unused; semantics derived from history zeros)
    const int*   cate_list = (const int*)d_in[4];
    const float* uW        = (const float*)d_in[5];
    const float* iW        = (const float*)d_in[6];
    const float* cW        = (const float*)d_in[7];
    const float* gamma     = (const float*)d_in[8];
    const float* beta      = (const float*)d_in[9];
    const float* W1        = (const float*)d_in[10];
    const float* b1        = (const float*)d_in[11];
    const float* a1        = (const float*)d_in[12];
    const float* W2        = (const float*)d_in[13];
    const float* b2        = (const float*)d_in[14];
    const float* a2        = (const float*)d_in[15];
    const float* W3        = (const float*)d_in[16];
    const float* b3        = (const float*)d_in[17];
    float* out = (float*)d_out;

    scan_kernel<<<16, 256>>>(history);
    embed_kernel<<<BATCH / RPB, 256>>>(user, item, history, cate_list, uW, iW, cW);
    finalize_kernel<<<1, 384>>>(gamma, beta);
    dim3 g1(BATCH / 128, 4);
    gemm1_kernel<<<g1, 256>>>(W1, b1, a1);
    gemm2_out_kernel<<<BATCH / 64, 256>>>(W2, b2, a2, W3, b3, out);
}